// round 5
// baseline (speedup 1.0000x reference)
#include <cuda_runtime.h>
#include <cuda_bf16.h>

#define N_NODES 50000
#define N_EDGES 800000
#define D 64
#define SCAN_BLK 1024
#define SCAN_NB  ((N_NODES + 1 + SCAN_BLK - 1) / SCAN_BLK)   // 49

// ---- device-global scratch (no allocations allowed) ----
// Invariant: g_count and g_scan_flag are zero at every kernel_launch entry
// (BSS-zero initially; reset-after-consume inside the pipeline each call).
__device__ int   g_count[N_NODES];
__device__ int   g_off[N_NODES + 1];
__device__ int   g_cursor[N_NODES];
__device__ __align__(16) int2  g_perm[N_EDGES];      // (src, edge)
__device__ __align__(16) float g_hsum[N_NODES * D];  // normalized aggregation
__device__ volatile int g_scan_tot[SCAN_NB];
__device__ volatile int g_scan_flag[SCAN_NB];

// ---------------------------------------------------------------------------
// K1: degree histogram over dst (int4 loads, 4 edges/thread).
// ---------------------------------------------------------------------------
__global__ void kgcn_hist_kernel(const int* __restrict__ dst) {
    int t = blockIdx.x * blockDim.x + threadIdx.x;
    if (t < N_EDGES / 4) {
        int4 d4 = reinterpret_cast<const int4*>(dst)[t];
        atomicAdd(&g_count[d4.x], 1);
        atomicAdd(&g_count[d4.y], 1);
        atomicAdd(&g_count[d4.z], 1);
        atomicAdd(&g_count[d4.w], 1);
    }
}

// ---------------------------------------------------------------------------
// K2: single-kernel exclusive scan (decoupled lookback over 49 blocks; all
// blocks are wave-1 resident so spinning on earlier blocks is deadlock-free).
// Also: g_off[N] = E, cursors initialized, g_count reset for the next call.
// ---------------------------------------------------------------------------
__global__ void __launch_bounds__(SCAN_BLK) kgcn_scan_kernel() {
    __shared__ int wsum[32];
    __shared__ int s_prefix;
    const int tid = threadIdx.x, b = blockIdx.x;
    const int i = b * SCAN_BLK + tid;

    int v = (i < N_NODES) ? g_count[i] : 0;

    int lane = tid & 31, wid = tid >> 5;
    int x = v;
    #pragma unroll
    for (int dd = 1; dd < 32; dd <<= 1) {
        int y = __shfl_up_sync(0xffffffffu, x, dd);
        if (lane >= dd) x += y;
    }
    if (lane == 31) wsum[wid] = x;
    __syncthreads();
    if (wid == 0) {
        int s = wsum[lane];
        #pragma unroll
        for (int dd = 1; dd < 32; dd <<= 1) {
            int y = __shfl_up_sync(0xffffffffu, s, dd);
            if (lane >= dd) s += y;
        }
        wsum[lane] = s;
    }
    __syncthreads();
    int incl = x + ((wid > 0) ? wsum[wid - 1] : 0);   // inclusive within block

    if (tid == SCAN_BLK - 1) {
        g_scan_tot[b] = incl;
        __threadfence();
        g_scan_flag[b] = 1;
    }

    // decoupled lookback: sum totals of all earlier blocks (b <= 48 -> <=2 iters/lane)
    if (tid < 32) {
        int sum = 0;
        for (int j = tid; j < b; j += 32) {
            while (g_scan_flag[j] == 0) { }
            sum += g_scan_tot[j];
        }
        #pragma unroll
        for (int o = 16; o; o >>= 1) sum += __shfl_xor_sync(0xffffffffu, sum, o);
        if (tid == 0) s_prefix = sum;
    }
    __syncthreads();

    int off = s_prefix + incl - v;    // exclusive global prefix
    if (i <= N_NODES) {
        g_off[i] = off;
        if (i < N_NODES) {
            g_cursor[i] = off;
            g_count[i] = 0;           // reset-after-consume
        }
    }
}

// ---------------------------------------------------------------------------
// K3: scatter edge records into CSR slots; also resets the scan flags.
// ---------------------------------------------------------------------------
__global__ void kgcn_scatter_kernel(const int* __restrict__ src,
                                    const int* __restrict__ dst) {
    int e = blockIdx.x * blockDim.x + threadIdx.x;
    if (e < SCAN_NB) g_scan_flag[e] = 0;              // reset-after-consume
    if (e >= N_EDGES) return;
    int d = dst[e];
    int pos = atomicAdd(&g_cursor[d], 1);
    g_perm[pos] = make_int2(src[e], e);
}

// ---------------------------------------------------------------------------
// K4: pull-aggregate. 16 lanes per node walk the node's in-edge list, compute
// ex = exp(dot(h_src[src], e)) locally, accumulate ex*hv and ex in registers,
// write the NORMALIZED sum once. No atomics, no scratch zeroing.
// ---------------------------------------------------------------------------
__global__ void kgcn_pull_kernel(const float* __restrict__ h_src,
                                 const float* __restrict__ e) {
    int tid  = blockIdx.x * blockDim.x + threadIdx.x;
    int node = tid >> 4;
    int sub  = tid & 15;
    if (node >= N_NODES) return;   // never taken: N*16 == grid exactly

    const unsigned mask = (threadIdx.x & 16) ? 0xFFFF0000u : 0x0000FFFFu;
    int beg = g_off[node];
    int end = g_off[node + 1];

    const float4* h4 = reinterpret_cast<const float4*>(h_src);
    const float4* e4 = reinterpret_cast<const float4*>(e);

    float4 acc = make_float4(0.f, 0.f, 0.f, 0.f);
    float den = 0.f;

    int2 p = make_int2(0, 0);
    if (beg < end) p = g_perm[beg];
    for (int i = beg; i < end; i++) {
        int2 pc = p;
        if (i + 1 < end) p = g_perm[i + 1];      // prefetch next record
        float4 hv = h4[(size_t)pc.x * 16 + sub];
        float4 ev = e4[(size_t)pc.y * 16 + sub];
        float dot = hv.x * ev.x + hv.y * ev.y + hv.z * ev.z + hv.w * ev.w;
        dot += __shfl_xor_sync(mask, dot, 1);
        dot += __shfl_xor_sync(mask, dot, 2);
        dot += __shfl_xor_sync(mask, dot, 4);
        dot += __shfl_xor_sync(mask, dot, 8);
        float ex = __expf(dot);                  // full dot in every lane
        den += ex;
        acc.x = fmaf(ex, hv.x, acc.x);
        acc.y = fmaf(ex, hv.y, acc.y);
        acc.z = fmaf(ex, hv.z, acc.z);
        acc.w = fmaf(ex, hv.w, acc.w);
    }

    float inv = (den > 0.f) ? (1.0f / den) : 0.f;
    reinterpret_cast<float4*>(g_hsum)[(size_t)node * 16 + sub] =
        make_float4(acc.x * inv, acc.y * inv, acc.z * inv, acc.w * inv);
}

// ---------------------------------------------------------------------------
// K5: out = concat(h_dst, h_sum) @ W^T + b   (64-node x 64-col block tile)
// ---------------------------------------------------------------------------
#define HS_STRIDE 33
__global__ void __launch_bounds__(256) kgcn_out_kernel(
        const float* __restrict__ h_dst,
        const float* __restrict__ W,
        const float* __restrict__ b,
        float* __restrict__ out) {
    __shared__ float W_s[128 * 64];          // [k][j] transposed, 32KB
    __shared__ float h_s[64 * HS_STRIDE];    // [local node][kk], padded

    const int tid = threadIdx.x;
    for (int i = tid; i < 64 * 128; i += 256) {
        int j = i >> 7;
        int k = i & 127;
        W_s[k * 64 + j] = W[i];
    }

    const int tx = tid & 15;      // cols 4*tx..4*tx+3
    const int ty = tid >> 4;      // nodes 4*ty..4*ty+3
    const int node0 = blockIdx.x * 64;

    float acc[4][4];
    #pragma unroll
    for (int n = 0; n < 4; n++)
        acc[n][0] = acc[n][1] = acc[n][2] = acc[n][3] = 0.f;

    #pragma unroll
    for (int c = 0; c < 4; c++) {
        const float* srcp = (c < 2) ? h_dst : g_hsum;
        const int kof4 = (c & 1) * 8;

        __syncthreads();
        #pragma unroll
        for (int r = 0; r < 2; r++) {
            int idx = tid + r * 256;    // 0..511
            int n   = idx >> 3;
            int q   = idx & 7;
            int gn  = node0 + n;
            float4 v = make_float4(0.f, 0.f, 0.f, 0.f);
            if (gn < N_NODES)
                v = reinterpret_cast<const float4*>(srcp)[(size_t)gn * 16 + kof4 + q];
            int base = n * HS_STRIDE + q * 4;
            h_s[base + 0] = v.x; h_s[base + 1] = v.y;
            h_s[base + 2] = v.z; h_s[base + 3] = v.w;
        }
        __syncthreads();

        const float* Wrow = &W_s[(c * 32) * 64 + 4 * tx];
        #pragma unroll 8
        for (int kk = 0; kk < 32; kk++) {
            float4 w = *reinterpret_cast<const float4*>(Wrow + kk * 64);
            #pragma unroll
            for (int n = 0; n < 4; n++) {
                float hv = h_s[(4 * ty + n) * HS_STRIDE + kk];
                acc[n][0] = fmaf(hv, w.x, acc[n][0]);
                acc[n][1] = fmaf(hv, w.y, acc[n][1]);
                acc[n][2] = fmaf(hv, w.z, acc[n][2]);
                acc[n][3] = fmaf(hv, w.w, acc[n][3]);
            }
        }
    }

    float4 bb = *reinterpret_cast<const float4*>(&b[4 * tx]);
    #pragma unroll
    for (int n = 0; n < 4; n++) {
        int gn = node0 + 4 * ty + n;
        if (gn < N_NODES) {
            float4 o = make_float4(acc[n][0] + bb.x, acc[n][1] + bb.y,
                                   acc[n][2] + bb.z, acc[n][3] + bb.w);
            reinterpret_cast<float4*>(out)[(size_t)gn * 16 + tx] = o;
        }
    }
}

// ---------------------------------------------------------------------------
// Launch.  Inputs: 0 h_src, 1 h_dst, 2 e, 3 src, 4 dst, 5 W, 6 b
// ---------------------------------------------------------------------------
extern "C" void kernel_launch(void* const* d_in, const int* in_sizes, int n_in,
                              void* d_out, int out_size) {
    const float* h_src = (const float*)d_in[0];
    const float* h_dst = (const float*)d_in[1];
    const float* e     = (const float*)d_in[2];
    const int*   src   = (const int*)d_in[3];
    const int*   dst   = (const int*)d_in[4];
    const float* W     = (const float*)d_in[5];
    const float* b     = (const float*)d_in[6];
    float* out = (float*)d_out;

    kgcn_hist_kernel<<<(N_EDGES / 4 + 255) / 256, 256>>>(dst);
    kgcn_scan_kernel<<<SCAN_NB, SCAN_BLK>>>();
    kgcn_scatter_kernel<<<(N_EDGES + 255) / 256, 256>>>(src, dst);
    kgcn_pull_kernel<<<(N_NODES * 16) / 256, 256>>>(h_src, e);   // 3125 blocks
    kgcn_out_kernel<<<(N_NODES + 63) / 64, 256>>>(h_dst, W, b, out);
}